// round 16
// baseline (speedup 1.0000x reference)
#include <cuda_runtime.h>
#include <cstdint>

#define NUM_NODES 50000
#define INPUT_SIZE 128
#define NUM_REL 16
#define NUM_EDGES 1600000
#define CLAMP_MIN 1e-5f
#define CLAMP_MAX 0.99999f

// Node logit table: T[n][0:16] = x[n].W_src, T[n][16:32] = x[n].W_dst
__device__ float g_table[NUM_NODES * 32];

// Packed f32x2 helpers (Blackwell FFMA2 — PTX-only).
__device__ __forceinline__ uint64_t pack2(float lo, float hi) {
    uint64_t r;
    asm("mov.b64 %0, {%1, %2};" : "=l"(r) : "f"(lo), "f"(hi));
    return r;
}
__device__ __forceinline__ void fma2(uint64_t& acc, uint64_t a, uint64_t b) {
    asm("fma.rn.f32x2 %0, %1, %2, %0;" : "+l"(acc) : "l"(a), "l"(b));
}
__device__ __forceinline__ float2 unpack2(uint64_t v) {
    float lo, hi;
    asm("mov.b64 {%0, %1}, %2;" : "=f"(lo), "=f"(hi) : "l"(v));
    return make_float2(lo, hi);
}

// ---------------------------------------------------------------------------
// Kernel A: 50000x128 @ 128x32 GEMM into g_table.
// 128 thr/block, 128-node tile, 8 nodes x 4 cols/thread as FFMA2 node-pairs.
// Double-buffered Xs with register-staged prefetch. XOR-swizzled Xs layout
// (node' = node ^ ((k>>2)<<2)): conflict-free stores AND reads, zero padding,
// so Ws(16K) + 2*Xs(16K each) = 48KB exactly (static smem cap).
// Measured: ~10.9us vs 10.3us fp32-FFMA issue roofline.
// ---------------------------------------------------------------------------
__global__ void __launch_bounds__(128) node_logits_kernel(
    const float* __restrict__ x, const float* __restrict__ W)
{
    __shared__ float Ws[INPUT_SIZE][32];     // 16 KB [k][r]
    __shared__ float Xs[2][32][128];         // 32 KB [buf][k][node^swz]

    const int tid = threadIdx.x;

    for (int idx = tid; idx < INPUT_SIZE * 32; idx += 128) {
        int k = idx >> 5;
        int r = idx & 31;
        Ws[k][r] = (r < NUM_REL) ? W[k * NUM_REL + r]
                                 : W[(k + INPUT_SIZE) * NUM_REL + (r - NUM_REL)];
    }

    const int node0 = blockIdx.x * 128;
    const int rg = tid & 7;    // 8 groups of 4 rel-cols
    const int ng = tid >> 3;   // 16 groups of 8 nodes

    int lrow[8], lc4[8];
    const float* lp[8];
#pragma unroll
    for (int it = 0; it < 8; ++it) {
        int s = tid + it * 128;      // 0..1023
        lrow[it] = s >> 3;           // node within tile 0..127
        lc4[it]  = s & 7;            // float4 within 32-float k-chunk
        int gr = node0 + lrow[it];
        if (gr >= NUM_NODES) gr = NUM_NODES - 1;   // dup loads OK
        lp[it] = &x[(size_t)gr * INPUT_SIZE + lc4[it] * 4];
    }

    uint64_t acc2[4][4];             // [node-pair][col]
#pragma unroll
    for (int i = 0; i < 4; ++i)
#pragma unroll
        for (int j = 0; j < 4; ++j) acc2[i][j] = 0ull;

    // Prologue: load chunk 0, stage into buffer 0 (swizzled).
    float4 v[8];
#pragma unroll
    for (int it = 0; it < 8; ++it)
        v[it] = *reinterpret_cast<const float4*>(lp[it]);
#pragma unroll
    for (int it = 0; it < 8; ++it) {
        int sw = lrow[it] ^ (lc4[it] << 2);
        Xs[0][lc4[it] * 4 + 0][sw] = v[it].x;
        Xs[0][lc4[it] * 4 + 1][sw] = v[it].y;
        Xs[0][lc4[it] * 4 + 2][sw] = v[it].z;
        Xs[0][lc4[it] * 4 + 3][sw] = v[it].w;
    }
    __syncthreads();

#pragma unroll
    for (int kc = 0; kc < 4; ++kc) {
        const int buf = kc & 1;

        // Prefetch chunk kc+1 into registers.
        if (kc < 3) {
#pragma unroll
            for (int it = 0; it < 8; ++it)
                v[it] = *reinterpret_cast<const float4*>(lp[it] + (kc + 1) * 32);
        }

        // Compute on current buffer.
#pragma unroll
        for (int kk = 0; kk < 32; ++kk) {
            int k = kc * 32 + kk;
            const int swz = (kk >> 2) << 2;    // compile-time per unrolled kk
            float4 wv = *reinterpret_cast<const float4*>(&Ws[k][rg * 4]);
            uint64_t wd[4] = { pack2(wv.x, wv.x), pack2(wv.y, wv.y),
                               pack2(wv.z, wv.z), pack2(wv.w, wv.w) };
            float4 xa = *reinterpret_cast<const float4*>(&Xs[buf][kk][(ng * 8) ^ swz]);
            float4 xb = *reinterpret_cast<const float4*>(&Xs[buf][kk][(ng * 8 + 4) ^ swz]);
            uint64_t xp[4] = { pack2(xa.x, xa.y), pack2(xa.z, xa.w),
                               pack2(xb.x, xb.y), pack2(xb.z, xb.w) };
#pragma unroll
            for (int i = 0; i < 4; ++i)
#pragma unroll
                for (int j = 0; j < 4; ++j)
                    fma2(acc2[i][j], xp[i], wd[j]);
        }

        // Stage prefetched chunk into the other buffer.
        if (kc < 3) {
#pragma unroll
            for (int it = 0; it < 8; ++it) {
                int sw = lrow[it] ^ (lc4[it] << 2);
                Xs[buf ^ 1][lc4[it] * 4 + 0][sw] = v[it].x;
                Xs[buf ^ 1][lc4[it] * 4 + 1][sw] = v[it].y;
                Xs[buf ^ 1][lc4[it] * 4 + 2][sw] = v[it].z;
                Xs[buf ^ 1][lc4[it] * 4 + 3][sw] = v[it].w;
            }
            __syncthreads();
        }
    }

#pragma unroll
    for (int i = 0; i < 4; ++i) {
        float2 c0 = unpack2(acc2[i][0]);
        float2 c1 = unpack2(acc2[i][1]);
        float2 c2 = unpack2(acc2[i][2]);
        float2 c3 = unpack2(acc2[i][3]);
        int n0 = node0 + ng * 8 + 2 * i;
        if (n0 < NUM_NODES)
            *reinterpret_cast<float4*>(&g_table[(size_t)n0 * 32 + rg * 4]) =
                make_float4(c0.x, c1.x, c2.x, c3.x);
        if (n0 + 1 < NUM_NODES)
            *reinterpret_cast<float4*>(&g_table[(size_t)(n0 + 1) * 32 + rg * 4]) =
                make_float4(c0.y, c1.y, c2.y, c3.y);
    }
}

// ---------------------------------------------------------------------------
// FMA/ALU-only clamped sigmoid (no MUFU; proven rel_err ~3e-7).
// ---------------------------------------------------------------------------
__device__ __forceinline__ float sigmoid_clamped(float v)
{
    v = fminf(fmaxf(v, -15.0f), 15.0f);
    float y = v * -1.4426950408889634f;
    float z = y + 12582912.0f;
    int   n = __float_as_int(z) - 0x4B400000;
    float f = y - (z - 12582912.0f);
    float p = 0.0013333558f;
    p = fmaf(p, f, 0.0096181291f);
    p = fmaf(p, f, 0.0555041086f);
    p = fmaf(p, f, 0.2402265069f);
    p = fmaf(p, f, 0.6931471806f);
    p = fmaf(p, f, 1.0f);
    float e = p * __int_as_float((n + 127) << 23);
    float d = 1.0f + e;
    float r = __int_as_float(0x7EF311C3 - __float_as_int(d));
    r = r * (2.0f - d * r);
    r = r * (2.0f - d * r);
    r = r * (2.0f - d * r);
    return fminf(fmaxf(r, CLAMP_MIN), CLAMP_MAX);
}

// ---------------------------------------------------------------------------
// Kernel B: 1 edge/thread (measured-best total; at the divergent-gather
// L1tex replay floor — invariant across occ/ILP/MUFU/cache-policy sweeps).
// ---------------------------------------------------------------------------
__global__ void __launch_bounds__(256) edge_kernel(
    const int* __restrict__ ei,
    const int* __restrict__ et,
    float* __restrict__ out)
{
    const int e = blockIdx.x * 256 + threadIdx.x;
    if (e < NUM_EDGES) {
        int s = ei[e];
        int d = ei[NUM_EDGES + e];
        int t = et[e];
        float a = __ldg(&g_table[s * 32 + t]);
        float b = __ldg(&g_table[d * 32 + 16 + t]);
        out[e] = sigmoid_clamped(a + b);
    }
}

extern "C" void kernel_launch(void* const* d_in, const int* in_sizes, int n_in,
                              void* d_out, int out_size)
{
    const float* x  = (const float*)d_in[0];
    const float* W  = (const float*)d_in[1];
    const int*   ei = (const int*)d_in[2];
    const int*   et = (const int*)d_in[3];
    float* out = (float*)d_out;

    const int node_blocks = (NUM_NODES + 127) / 128;       // 391
    node_logits_kernel<<<node_blocks, 128>>>(x, W);

    const int edge_blocks = (NUM_EDGES + 255) / 256;       // 6250
    edge_kernel<<<edge_blocks, 256>>>(ei, et, out);
}